// round 2
// baseline (speedup 1.0000x reference)
#include <cuda_runtime.h>

#define NN 50000
#define FF 64
#define EE 800000

// Scratch (device globals — no allocation allowed).
// float4 arrays force 16B alignment for red.global.add.v4.f32.
__device__ float4 g_s4[NN * 16];    // neighbor-sum accumulator [N,64]
__device__ float4 g_h14[NN * 16];   // layer-1 activations     [N,64]
__device__ int    g_cnt[NN];        // in-degree per node

// ---------------------------------------------------------------------------
// Zero the accumulator (and optionally the degree counters).
// ---------------------------------------------------------------------------
__global__ void zero_kernel(int zero_cnt) {
    int i = blockIdx.x * blockDim.x + threadIdx.x;
    if (i < NN * 16) g_s4[i] = make_float4(0.f, 0.f, 0.f, 0.f);
    if (zero_cnt && i < NN) g_cnt[i] = 0;
}

// ---------------------------------------------------------------------------
// Edge scatter: 16 threads per edge, each moves one float4 chunk of the
// 64-float feature row: s[dst] += feat[src].  Vectorized global reduction
// (red.global.add.v4.f32, sm_90+) quarters the atomic-op count.
// edge_index is int32 (JAX default x64-disabled downcasts int64 -> int32).
// ---------------------------------------------------------------------------
template <bool DO_COUNT>
__global__ __launch_bounds__(256) void scatter_kernel(
    const float* __restrict__ feat,
    const int* __restrict__ src,
    const int* __restrict__ dst)
{
    int i = blockIdx.x * blockDim.x + threadIdx.x;
    if (i >= EE * 16) return;
    int e = i >> 4;
    int c = i & 15;
    int s = src[e];   // broadcast within the 16-thread group (L1 hit)
    int d = dst[e];

    float4 v = *((const float4*)feat + s * 16 + c);
    float4* addr = g_s4 + d * 16 + c;
    asm volatile("red.global.add.v4.f32 [%0], {%1,%2,%3,%4};"
                 :: "l"(addr), "f"(v.x), "f"(v.y), "f"(v.z), "f"(v.w)
                 : "memory");

    if (DO_COUNT && c == 0) atomicAdd(&g_cnt[d], 1);
}

// ---------------------------------------------------------------------------
// Fused mean + concat + linear (+bias, optional ReLU):
//   out[n][o] = act( b[o] + sum_k [x[n] || s[n]/max(cnt,1)][k] * W[k][o] )
// Block tile: 64 nodes x 64 outputs. 256 threads, each computes a 4x4
// register tile. W (128x64 = 32KB) and the assembled input tile
// (64x128, padded rows) staged in dynamic smem (66560 B total).
// ---------------------------------------------------------------------------
#define IN_PITCH 132   // 128 + 4 pad; 132*4 bytes = 528 = 33*16 (float4-aligned)

template <bool RELU>
__global__ __launch_bounds__(256) void sage_linear_kernel(
    const float* __restrict__ xin,
    const float* __restrict__ W,
    const float* __restrict__ b,
    float* __restrict__ out)
{
    extern __shared__ float smem[];
    float* sW  = smem;            // [128*64]
    float* sIn = smem + 128 * 64; // [64][IN_PITCH]

    int tid = threadIdx.x;
    int n0  = blockIdx.x * 64;

    // Stage W (2048 float4, 8 per thread)
    {
        const float4* W4 = (const float4*)W;
        float4* sW4 = (float4*)sW;
        #pragma unroll
        for (int i = 0; i < 8; i++) sW4[tid + i * 256] = W4[tid + i * 256];
    }

    // Stage input tile: [x_row || s_row/max(cnt,1)] per node
    const float* sbuf = (const float*)g_s4;
    for (int idx = tid; idx < 64 * 128; idx += 256) {
        int ni = idx >> 7;
        int k  = idx & 127;
        int node = n0 + ni;
        float v = 0.f;
        if (node < NN) {
            if (k < 64) {
                v = xin[node * 64 + k];
            } else {
                float cf = (float)g_cnt[node];
                v = sbuf[node * 64 + (k - 64)] / fmaxf(cf, 1.0f);
            }
        }
        sIn[ni * IN_PITCH + k] = v;
    }
    __syncthreads();

    int tx = tid & 15;   // output group: columns tx*4 .. tx*4+3
    int ty = tid >> 4;   // node group:   rows   ty*4 .. ty*4+3

    float acc[4][4];
    #pragma unroll
    for (int j = 0; j < 4; j++)
        #pragma unroll
        for (int q = 0; q < 4; q++) acc[j][q] = 0.f;

    float bb[4];
    #pragma unroll
    for (int q = 0; q < 4; q++) bb[q] = b[tx * 4 + q];

    #pragma unroll
    for (int k4 = 0; k4 < 128; k4 += 4) {
        float a[4][4];
        #pragma unroll
        for (int j = 0; j < 4; j++) {
            float4 av = *(const float4*)&sIn[(ty * 4 + j) * IN_PITCH + k4];
            a[j][0] = av.x; a[j][1] = av.y; a[j][2] = av.z; a[j][3] = av.w;
        }
        #pragma unroll
        for (int kk = 0; kk < 4; kk++) {
            float4 w = *(const float4*)&sW[(k4 + kk) * 64 + tx * 4];
            #pragma unroll
            for (int j = 0; j < 4; j++) {
                acc[j][0] += a[j][kk] * w.x;
                acc[j][1] += a[j][kk] * w.y;
                acc[j][2] += a[j][kk] * w.z;
                acc[j][3] += a[j][kk] * w.w;
            }
        }
    }

    #pragma unroll
    for (int j = 0; j < 4; j++) {
        int node = n0 + ty * 4 + j;
        if (node < NN) {
            float4 r;
            r.x = acc[j][0] + bb[0];
            r.y = acc[j][1] + bb[1];
            r.z = acc[j][2] + bb[2];
            r.w = acc[j][3] + bb[3];
            if (RELU) {
                r.x = fmaxf(r.x, 0.f); r.y = fmaxf(r.y, 0.f);
                r.z = fmaxf(r.z, 0.f); r.w = fmaxf(r.w, 0.f);
            }
            *(float4*)&out[node * 64 + tx * 4] = r;
        }
    }
}

// ---------------------------------------------------------------------------
extern "C" void kernel_launch(void* const* d_in, const int* in_sizes, int n_in,
                              void* d_out, int out_size)
{
    const float* x   = (const float*)d_in[0];
    const int*   ei  = (const int*)d_in[1];   // int32 edge_index [2, E]
    const float* W1  = (const float*)d_in[2];
    const float* b1  = (const float*)d_in[3];
    const float* W2  = (const float*)d_in[4];
    const float* b2  = (const float*)d_in[5];
    float*       out = (float*)d_out;

    const int* src = ei;        // edge_index[0]
    const int* dst = ei + EE;   // edge_index[1]

    void* h1p = nullptr;
    cudaGetSymbolAddress(&h1p, g_h14);
    float* h1 = (float*)h1p;

    const int SMEM_LIN = (128 * 64 + 64 * IN_PITCH) * (int)sizeof(float); // 66560
    cudaFuncSetAttribute(sage_linear_kernel<true>,
                         cudaFuncAttributeMaxDynamicSharedMemorySize, SMEM_LIN);
    cudaFuncSetAttribute(sage_linear_kernel<false>,
                         cudaFuncAttributeMaxDynamicSharedMemorySize, SMEM_LIN);

    const int ZB  = (NN * 16 + 255) / 256;
    const int SB  = (EE * 16) / 256;
    const int LB  = (NN + 63) / 64;

    // Layer 1
    zero_kernel<<<ZB, 256>>>(1);
    scatter_kernel<true><<<SB, 256>>>(x, src, dst);
    sage_linear_kernel<true><<<LB, 256, SMEM_LIN>>>(x, W1, b1, h1);

    // Layer 2
    zero_kernel<<<ZB, 256>>>(0);
    scatter_kernel<false><<<SB, 256>>>(h1, src, dst);
    sage_linear_kernel<false><<<LB, 256, SMEM_LIN>>>(h1, W2, b2, out);
}